// round 13
// baseline (speedup 1.0000x reference)
#include <cuda_runtime.h>
#include <cuda_bf16.h>
#include <cstdint>

// ---------------------------------------------------------------------------
// RNN Autoencoder (GRU enc/dec), B=512, T=180, H=256, LAT=128
//   32 blocks x 256 threads, 16 batch rows per block.
//   bf16 hi/lo split tensor-core GEMMs (3 mma products per tile).
//   Weights packed once per launch into mma B-fragment order.
//   enc and dec are separate launches (fc_dec reshape scrambles batch).
// ---------------------------------------------------------------------------

#define T_LEN 180
#define HID   256
#define BT    16
#define HS    264               // smem row stride in floats (8 mod 32)
#define PACK_PER_MAT 196608     // 96 ntiles * 16 ktiles * 32 lanes * 4 u32
#define RECON_ELEMS  (512 * T_LEN * 2)   // 184320

__device__ __align__(16) unsigned g_pack[6 * PACK_PER_MAT]; // 6 matrices, packed
__device__ float g_xn[512 * T_LEN * 2];                      // layernormed input
__device__ float g_fcdec[512 * 512];                         // fc_dec output flat

// ---------------------------------------------------------------------------
__device__ __forceinline__ float sigm(float x) {
    return __fdividef(1.f, 1.f + __expf(-x));
}
__device__ __forceinline__ float tanh_(float x) {
    float ax = fabsf(x);
    float e  = __expf(-2.f * ax);
    float t  = __fdividef(1.f - e, 1.f + e);
    return copysignf(t, x);
}

// split floats (x,y) into bf16 hi pair and bf16 residual-lo pair (packed bf16x2)
__device__ __forceinline__ void splitf2(float x, float y, unsigned& hi, unsigned& lo) {
    __nv_bfloat16 hx = __float2bfloat16(x);
    __nv_bfloat16 hy = __float2bfloat16(y);
    __nv_bfloat16 lx = __float2bfloat16(x - __bfloat162float(hx));
    __nv_bfloat16 ly = __float2bfloat16(y - __bfloat162float(hy));
    hi = ((unsigned)__bfloat16_as_ushort(hy) << 16) | (unsigned)__bfloat16_as_ushort(hx);
    lo = ((unsigned)__bfloat16_as_ushort(ly) << 16) | (unsigned)__bfloat16_as_ushort(lx);
}

__device__ __forceinline__ void mma16816(float* c, const unsigned* a, unsigned b0, unsigned b1) {
    asm volatile(
        "mma.sync.aligned.m16n8k16.row.col.f32.bf16.bf16.f32 "
        "{%0,%1,%2,%3},{%4,%5,%6,%7},{%8,%9},{%0,%1,%2,%3};\n"
        : "+f"(c[0]), "+f"(c[1]), "+f"(c[2]), "+f"(c[3])
        : "r"(a[0]), "r"(a[1]), "r"(a[2]), "r"(a[3]), "r"(b0), "r"(b1));
}

// ---------------------------------------------------------------------------
// pack: W (768x256 row-major) -> per-lane B-fragment order with hi/lo split.
//   u32 offset = m*PACK_PER_MAT + ((nt*16+kt)*32 + lane)*4
//   n = nt*8 + lane/4 ; k0 = kt*16 + (lane%4)*2 ; values {b0hi,b1hi,b0lo,b1lo}
// ---------------------------------------------------------------------------
__global__ void pack_kernel(const float* __restrict__ w0, const float* __restrict__ w1,
                            const float* __restrict__ w2, const float* __restrict__ w3,
                            const float* __restrict__ w4, const float* __restrict__ w5) {
    int tid = blockIdx.x * blockDim.x + threadIdx.x;
    if (tid >= 6 * 49152) return;
    int m   = tid / 49152;
    int rem = tid % 49152;
    int nt  = rem >> 9;
    int kt  = (rem >> 5) & 15;
    int t   = rem & 31;
    const float* W = (m == 0) ? w0 : (m == 1) ? w1 : (m == 2) ? w2
                   : (m == 3) ? w3 : (m == 4) ? w4 : w5;
    int n  = nt * 8 + (t >> 2);
    int k0 = kt * 16 + (t & 3) * 2;
    const float* row = W + n * HID;
    unsigned h0, l0, h1, l1;
    splitf2(row[k0],     row[k0 + 1], h0, l0);
    splitf2(row[k0 + 8], row[k0 + 9], h1, l1);
    unsigned* dst = g_pack + m * PACK_PER_MAT + (((nt * 16 + kt) * 32 + t) << 2);
    uint4 v; v.x = h0; v.y = h1; v.z = l0; v.w = l1;
    *(uint4*)dst = v;
}

// ---------------------------------------------------------------------------
// layernorm over the (T,2)=360 values of each batch row (population var)
// ---------------------------------------------------------------------------
__global__ void ln_kernel(const float* __restrict__ x, const float* __restrict__ lw,
                          const float* __restrict__ lb) {
    int b = blockIdx.x;
    const float* xb = x + b * 360;
    float s = 0.f, s2 = 0.f;
    for (int i = threadIdx.x; i < 360; i += blockDim.x) {
        float v = xb[i]; s += v; s2 += v * v;
    }
    __shared__ float sh[8];
    for (int o = 16; o; o >>= 1) {
        s  += __shfl_down_sync(0xffffffffu, s, o);
        s2 += __shfl_down_sync(0xffffffffu, s2, o);
    }
    int wid = threadIdx.x >> 5;
    if ((threadIdx.x & 31) == 0) { sh[wid] = s; sh[4 + wid] = s2; }
    __syncthreads();
    if (threadIdx.x == 0) {
        float ts = sh[0] + sh[1] + sh[2] + sh[3];
        float t2 = sh[4] + sh[5] + sh[6] + sh[7];
        float mu = ts * (1.f / 360.f);
        float var = t2 * (1.f / 360.f) - mu * mu;
        sh[0] = mu;
        sh[1] = rsqrtf(var + 1e-5f);
    }
    __syncthreads();
    float mu = sh[0], rstd = sh[1];
    for (int i = threadIdx.x; i < 360; i += blockDim.x)
        g_xn[b * 360 + i] = (xb[i] - mu) * rstd * lw[i] + lb[i];
}

// ---------------------------------------------------------------------------
// core warp-GEMM: accumulate src(16 x 256 fp32 smem) @ W^T into per-gate accums
// warp w owns h-columns [32w, 32w+32) -> ntiles {g*32 + 4w + j}
// ---------------------------------------------------------------------------
__device__ __forceinline__ void gemm_acc(const float* __restrict__ src,
                                         const unsigned* __restrict__ P,
                                         float Cr[4][4], float Cz[4][4], float Cn[4][4],
                                         int w, int lane) {
    const int r0 = lane >> 2, q = lane & 3;
    const float* s0 = src + r0 * HS;
    const float* s1 = src + (r0 + 8) * HS;
#pragma unroll 4
    for (int kt = 0; kt < 16; kt++) {
        const int kc = kt * 16 + q * 2;
        unsigned ah[4], al[4];
        float2 v0 = *(const float2*)(s0 + kc);
        float2 v1 = *(const float2*)(s1 + kc);
        float2 v2 = *(const float2*)(s0 + kc + 8);
        float2 v3 = *(const float2*)(s1 + kc + 8);
        splitf2(v0.x, v0.y, ah[0], al[0]);
        splitf2(v1.x, v1.y, ah[1], al[1]);
        splitf2(v2.x, v2.y, ah[2], al[2]);
        splitf2(v3.x, v3.y, ah[3], al[3]);
        const unsigned* Pk = P + (kt * 32 + lane) * 4;
#pragma unroll
        for (int j = 0; j < 4; j++) {
            int nt = w * 4 + j;
            uint4 Br = *(const uint4*)(Pk + (unsigned)(nt)      * 2048u);
            uint4 Bz = *(const uint4*)(Pk + (unsigned)(nt + 32) * 2048u);
            uint4 Bn = *(const uint4*)(Pk + (unsigned)(nt + 64) * 2048u);
            mma16816(Cr[j], ah, Br.x, Br.y);
            mma16816(Cr[j], ah, Br.z, Br.w);
            mma16816(Cr[j], al, Br.x, Br.y);
            mma16816(Cz[j], ah, Bz.x, Bz.y);
            mma16816(Cz[j], ah, Bz.z, Bz.w);
            mma16816(Cz[j], al, Bz.x, Bz.y);
            mma16816(Cn[j], ah, Bn.x, Bn.y);
            mma16816(Cn[j], ah, Bn.z, Bn.w);
            mma16816(Cn[j], al, Bn.x, Bn.y);
        }
    }
}

// init accumulators with biases: r,z get bih+bhh ; n keeps ih (Cin) / hh (Chn) split
__device__ __forceinline__ void init_gates(float Crz[2][4][4], float Cin[4][4], float Chn[4][4],
                                           const float* __restrict__ bih,
                                           const float* __restrict__ bhh, int w, int q) {
#pragma unroll
    for (int j = 0; j < 4; j++) {
        int cb = 32 * w + 8 * j + q * 2;
#pragma unroll
        for (int g = 0; g < 2; g++) {
            float2 bi = *(const float2*)(bih + g * 256 + cb);
            float2 bh = *(const float2*)(bhh + g * 256 + cb);
            Crz[g][j][0] = bi.x + bh.x; Crz[g][j][1] = bi.y + bh.y;
            Crz[g][j][2] = bi.x + bh.x; Crz[g][j][3] = bi.y + bh.y;
        }
        float2 bin = *(const float2*)(bih + 512 + cb);
        float2 bhn = *(const float2*)(bhh + 512 + cb);
        Cin[j][0] = bin.x; Cin[j][1] = bin.y; Cin[j][2] = bin.x; Cin[j][3] = bin.y;
        Chn[j][0] = bhn.x; Chn[j][1] = bhn.y; Chn[j][2] = bhn.x; Chn[j][3] = bhn.y;
    }
}

// scalar ih path for 2-dim inputs: Wih is (768,2) row-major
__device__ __forceinline__ void add_x2(float Crz[2][4][4], float Cin[4][4],
                                       const float* __restrict__ Wih,
                                       float xa0, float xa1, float xb0, float xb1,
                                       int w, int q) {
#pragma unroll
    for (int j = 0; j < 4; j++) {
        int cb = 32 * w + 8 * j + q * 2;
#pragma unroll
        for (int g = 0; g < 3; g++) {
            int c0 = g * 256 + cb;
            float2 w0 = *(const float2*)(Wih + c0 * 2);
            float2 w1 = *(const float2*)(Wih + (c0 + 1) * 2);
            float g0a = xa0 * w0.x + xa1 * w0.y;
            float g1a = xa0 * w1.x + xa1 * w1.y;
            float g0b = xb0 * w0.x + xb1 * w0.y;
            float g1b = xb0 * w1.x + xb1 * w1.y;
            if (g < 2) {
                Crz[g][j][0] += g0a; Crz[g][j][1] += g1a;
                Crz[g][j][2] += g0b; Crz[g][j][3] += g1b;
            } else {
                Cin[j][0] += g0a; Cin[j][1] += g1a;
                Cin[j][2] += g0b; Cin[j][3] += g1b;
            }
        }
    }
}

// GRU gate combine + in-place smem h update (call between __syncthreads())
__device__ __forceinline__ void combine_store(float* __restrict__ hs,
                                              float Crz[2][4][4], float Cin[4][4],
                                              float Chn[4][4], int w, int r0, int q) {
#pragma unroll
    for (int j = 0; j < 4; j++) {
        int cb = 32 * w + 8 * j + q * 2;
        float2 hA = *(float2*)(hs + r0 * HS + cb);
        float2 hB = *(float2*)(hs + (r0 + 8) * HS + cb);
        float rg, zg, ng;
        rg = sigm(Crz[0][j][0]); zg = sigm(Crz[1][j][0]);
        ng = tanh_(Cin[j][0] + rg * Chn[j][0]);
        hA.x = (1.f - zg) * ng + zg * hA.x;
        rg = sigm(Crz[0][j][1]); zg = sigm(Crz[1][j][1]);
        ng = tanh_(Cin[j][1] + rg * Chn[j][1]);
        hA.y = (1.f - zg) * ng + zg * hA.y;
        rg = sigm(Crz[0][j][2]); zg = sigm(Crz[1][j][2]);
        ng = tanh_(Cin[j][2] + rg * Chn[j][2]);
        hB.x = (1.f - zg) * ng + zg * hB.x;
        rg = sigm(Crz[0][j][3]); zg = sigm(Crz[1][j][3]);
        ng = tanh_(Cin[j][3] + rg * Chn[j][3]);
        hB.y = (1.f - zg) * ng + zg * hB.y;
        *(float2*)(hs + r0 * HS + cb) = hA;
        *(float2*)(hs + (r0 + 8) * HS + cb) = hB;
    }
}

// ---------------------------------------------------------------------------
// encoder: 2-layer GRU scan + fc_enc (-> z output) + fc_dec (-> g_fcdec)
// ---------------------------------------------------------------------------
__global__ void __launch_bounds__(256, 1) enc_kernel(
    const float* __restrict__ Wih0, const float* __restrict__ bih0,
    const float* __restrict__ bhh0, const float* __restrict__ bih1,
    const float* __restrict__ bhh1,
    const float* __restrict__ fce_w, const float* __restrict__ fce_b,
    const float* __restrict__ fcd_w, const float* __restrict__ fcd_b,
    float* __restrict__ out) {
    __shared__ float h0s[16 * HS];
    __shared__ float h1s[16 * HS];
    __shared__ float zs[16 * 132];

    const int tid = threadIdx.x;
    const int w = tid >> 5, lane = tid & 31;
    const int r0 = lane >> 2, q = lane & 3;
    const int bg = blockIdx.x * BT;

    for (int i = tid; i < 16 * HS; i += 256) { h0s[i] = 0.f; h1s[i] = 0.f; }
    __syncthreads();

    const unsigned* P0 = g_pack;                      // enc_Whh0
    const unsigned* P1 = g_pack + PACK_PER_MAT;       // enc_Wih1
    const unsigned* P2 = g_pack + 2 * PACK_PER_MAT;   // enc_Whh1

    for (int t = 0; t < T_LEN; t++) {
        float Crz[2][4][4], Cin[4][4], Chn[4][4];
        // ---- layer 0 ----
        init_gates(Crz, Cin, Chn, bih0, bhh0, w, q);
        {
            const float* xr = g_xn + (bg + r0) * 360 + t * 2;
            const float* xs = g_xn + (bg + r0 + 8) * 360 + t * 2;
            add_x2(Crz, Cin, Wih0, xr[0], xr[1], xs[0], xs[1], w, q);
        }
        gemm_acc(h0s, P0, Crz[0], Crz[1], Chn, w, lane);
        __syncthreads();
        combine_store(h0s, Crz, Cin, Chn, w, r0, q);
        __syncthreads();
        // ---- layer 1 ----
        init_gates(Crz, Cin, Chn, bih1, bhh1, w, q);
        gemm_acc(h0s, P1, Crz[0], Crz[1], Cin, w, lane);  // ih side
        gemm_acc(h1s, P2, Crz[0], Crz[1], Chn, w, lane);  // hh side
        __syncthreads();
        combine_store(h1s, Crz, Cin, Chn, w, r0, q);
        __syncthreads();
    }

    // ---- fc_enc: z = tanh(h1 @ W^T + b) ; write z to output tail ----
    for (int o = tid; o < 16 * 128; o += 256) {
        int row = o >> 7, lat = o & 127;
        float sum = fce_b[lat];
        const float* wr = fce_w + lat * 256;
        const float* hr = h1s + row * HS;
        for (int k = 0; k < 256; k++) sum += hr[k] * wr[k];
        float zv = tanh_(sum);
        zs[row * 132 + lat] = zv;
        out[RECON_ELEMS + (bg + row) * 128 + lat] = zv;
    }
    __syncthreads();

    // ---- fc_dec: (16 x 128) @ (128 -> 512) -> g_fcdec flat ----
    for (int o = tid; o < 16 * 512; o += 256) {
        int row = o >> 9, c = o & 511;
        float sum = fcd_b[c];
        const float* wr = fcd_w + c * 128;
        const float* zr = zs + row * 132;
        for (int k = 0; k < 128; k++) sum += zr[k] * wr[k];
        g_fcdec[(bg + row) * 512 + c] = sum;
    }
}

// ---------------------------------------------------------------------------
// decoder: autoregressive 2-layer GRU + fc_out each step
// initial states come from g_fcdec via the raw reshape(NL,B,H) view
// ---------------------------------------------------------------------------
__global__ void __launch_bounds__(256, 1) dec_kernel(
    const float* __restrict__ Wih0, const float* __restrict__ bih0,
    const float* __restrict__ bhh0, const float* __restrict__ bih1,
    const float* __restrict__ bhh1,
    const float* __restrict__ fco_w, const float* __restrict__ fco_b,
    float* __restrict__ out) {
    __shared__ float h0s[16 * HS];
    __shared__ float h1s[16 * HS];
    __shared__ float ys[32];

    const int tid = threadIdx.x;
    const int w = tid >> 5, lane = tid & 31;
    const int r0 = lane >> 2, q = lane & 3;
    const int bg = blockIdx.x * BT;

    // reshape(2,512,256) of flat (512,512): h[l][bb][h] = flat[l*131072 + bb*256 + h]
    for (int i = tid; i < 16 * 256; i += 256) {
        int row = i >> 8, col = i & 255;
        h0s[row * HS + col] = g_fcdec[(bg + row) * 256 + col];
        h1s[row * HS + col] = g_fcdec[131072 + (bg + row) * 256 + col];
    }
    if (tid < 32) ys[tid] = 0.f;
    __syncthreads();

    const unsigned* P3 = g_pack + 3 * PACK_PER_MAT;   // dec_Whh0
    const unsigned* P4 = g_pack + 4 * PACK_PER_MAT;   // dec_Wih1
    const unsigned* P5 = g_pack + 5 * PACK_PER_MAT;   // dec_Whh1

    for (int t = 0; t < T_LEN; t++) {
        float Crz[2][4][4], Cin[4][4], Chn[4][4];
        // ---- layer 0 (input = previous y, 2-dim) ----
        init_gates(Crz, Cin, Chn, bih0, bhh0, w, q);
        add_x2(Crz, Cin, Wih0, ys[r0 * 2], ys[r0 * 2 + 1],
               ys[(r0 + 8) * 2], ys[(r0 + 8) * 2 + 1], w, q);
        gemm_acc(h0s, P3, Crz[0], Crz[1], Chn, w, lane);
        __syncthreads();
        combine_store(h0s, Crz, Cin, Chn, w, r0, q);
        __syncthreads();
        // ---- layer 1 ----
        init_gates(Crz, Cin, Chn, bih1, bhh1, w, q);
        gemm_acc(h0s, P4, Crz[0], Crz[1], Cin, w, lane);
        gemm_acc(h1s, P5, Crz[0], Crz[1], Chn, w, lane);
        __syncthreads();
        combine_store(h1s, Crz, Cin, Chn, w, r0, q);
        __syncthreads();
        // ---- fc_out: y = h1 @ W^T + b  (32 outputs, 8 threads each) ----
        {
            int oi = tid >> 3, part = tid & 7;     // oi: 0..31
            int row = oi >> 1, od = oi & 1;
            const float* hr = h1s + row * HS + part * 32;
            const float* wr = fco_w + od * 256 + part * 32;
            float sum = 0.f;
#pragma unroll 8
            for (int k = 0; k < 32; k++) sum += hr[k] * wr[k];
            sum += __shfl_down_sync(0xffffffffu, sum, 4);
            sum += __shfl_down_sync(0xffffffffu, sum, 2);
            sum += __shfl_down_sync(0xffffffffu, sum, 1);
            if (part == 0) {
                float val = sum + fco_b[od];
                out[(bg + row) * 360 + t * 2 + od] = val;
                ys[row * 2 + od] = val;
            }
        }
        __syncthreads();
    }
}

// ---------------------------------------------------------------------------
extern "C" void kernel_launch(void* const* d_in, const int* in_sizes, int n_in,
                              void* d_out, int out_size) {
    const float* x        = (const float*)d_in[0];
    const float* ln_w     = (const float*)d_in[1];
    const float* ln_b     = (const float*)d_in[2];
    const float* enc_Wih0 = (const float*)d_in[3];
    const float* enc_Whh0 = (const float*)d_in[4];
    const float* enc_bih0 = (const float*)d_in[5];
    const float* enc_bhh0 = (const float*)d_in[6];
    const float* enc_Wih1 = (const float*)d_in[7];
    const float* enc_Whh1 = (const float*)d_in[8];
    const float* enc_bih1 = (const float*)d_in[9];
    const float* enc_bhh1 = (const float*)d_in[10];
    const float* dec_Wih0 = (const float*)d_in[11];
    const float* dec_Whh0 = (const float*)d_in[12];
    const float* dec_bih0 = (const float*)d_in[13];
    const float* dec_bhh0 = (const float*)d_in[14];
    const float* dec_Wih1 = (const float*)d_in[15];
    const float* dec_Whh1 = (const float*)d_in[16];
    const float* dec_bih1 = (const float*)d_in[17];
    const float* dec_bhh1 = (const float*)d_in[18];
    const float* fc_enc_w = (const float*)d_in[19];
    const float* fc_enc_b = (const float*)d_in[20];
    const float* fc_dec_w = (const float*)d_in[21];
    const float* fc_dec_b = (const float*)d_in[22];
    const float* fc_out_w = (const float*)d_in[23];
    const float* fc_out_b = (const float*)d_in[24];
    float* out = (float*)d_out;

    pack_kernel<<<1152, 256>>>(enc_Whh0, enc_Wih1, enc_Whh1,
                               dec_Whh0, dec_Wih1, dec_Whh1);
    ln_kernel<<<512, 128>>>(x, ln_w, ln_b);
    enc_kernel<<<32, 256>>>(enc_Wih0, enc_bih0, enc_bhh0, enc_bih1, enc_bhh1,
                            fc_enc_w, fc_enc_b, fc_dec_w, fc_dec_b, out);
    dec_kernel<<<32, 256>>>(dec_Wih0, dec_bih0, dec_bhh0, dec_bih1, dec_bhh1,
                            fc_out_w, fc_out_b, out);
}